// round 6
// baseline (speedup 1.0000x reference)
#include <cuda_runtime.h>

// PerLeadTimeLSTM: B=131072, LEADS=42, INPUT_DIM=2, HIDDEN=10.
// f-gate dead (c0=0):  y = W_fc @ (sigmoid(o) * tanh(sigmoid(i)*tanh(g))) + b_fc
// R6 = R5 resubmitted verbatim (R5 hit a GPU-broker capacity timeout; never ran).
// f32x2 math with register-pressure fixes:
//   - weights stored in smem PRE-DUPLICATED as (w,w) pairs -> LDS.64 gives a
//     ready broadcast operand, no pk MOVs, no long-lived packed weights
//   - j-loop NOT unrolled (11 weight u64s live per iter, not 110)
//   - NB=4 single pass (16 data regs), __launch_bounds__(256,4) caps 64 regs
// 3 MUFU/elem (tanh(c) -> deg-4 poly in c^2, |c|<1).

#define B_TOT   131072
#define T_LEADS 42
#define HID     10
#define NB      4
#define NTH_TOTAL (B_TOT * T_LEADS / NB)   // 1376256 threads, exact
#define BLOCK   256
#define PSU     113   // per-lead stride in u64 units (== 1 mod 16: conflict-free LDS.64)

typedef unsigned long long u64;

__device__ __forceinline__ float tanh_apx(float x) {
    float r;
    asm("tanh.approx.f32 %0, %1;" : "=f"(r) : "f"(x));
    return r;
}
__device__ __forceinline__ u64 pk(float lo, float hi) {
    u64 r; asm("mov.b64 %0, {%1, %2};" : "=l"(r) : "f"(lo), "f"(hi)); return r;
}
__device__ __forceinline__ void upk(u64 v, float& lo, float& hi) {
    asm("mov.b64 {%0, %1}, %2;" : "=f"(lo), "=f"(hi) : "l"(v));
}
__device__ __forceinline__ u64 fma2(u64 a, u64 b, u64 c) {
    u64 r; asm("fma.rn.f32x2 %0, %1, %2, %3;" : "=l"(r) : "l"(a), "l"(b), "l"(c)); return r;
}
__device__ __forceinline__ u64 mul2(u64 a, u64 b) {
    u64 r; asm("mul.rn.f32x2 %0, %1, %2;" : "=l"(r) : "l"(a), "l"(b)); return r;
}

// tanh(x)/x as deg-4 poly in u=x^2 on [0,1] (max err ~1e-4)
#define PA4  0.010659f
#define PA3 -0.0484815f
#define PA2  0.1332532f
#define PA1 -0.3338783f
#define PA0  1.0001009f

__global__ __launch_bounds__(BLOCK, 4)
void perlead_lstm_kernel(
    const float* __restrict__ x,      // (B, 42, 2)
    const float* __restrict__ W_ih,   // (42, 40, 2)
    const float* __restrict__ b_ih,   // (42, 40)
    const float* __restrict__ b_hh,   // (42, 40)
    const float* __restrict__ W_fc,   // (42, 2, 10)
    const float* __restrict__ b_fc,   // (42, 2)
    float* __restrict__ y_out)        // (B, 42, 2)
{
    // Per-lead layout in u64 units:
    //   j*11 + {0:wi0h, 1:wi1h, 2:wg0, 3:wg1, 4:wo0h, 5:wo1h,
    //           6:bih, 7:bg, 8:boh, 9:f0, 10:f1}   (j = 0..9; *h = pre-scaled 0.5)
    //   110: (bf0,bf0)  111: (bf1,bf1)
    // Every u64 holds the value DUPLICATED in both halves.
    __shared__ __align__(16) float2 wsh[T_LEADS * PSU];

    for (int idx = threadIdx.x; idx < T_LEADS * 112; idx += BLOCK) {
        int t = idx / 112;
        int off = idx % 112;
        float v;
        if (off < 110) {
            int j = off / 11, r = off % 11;
            if (r < 6) {
                int d = r & 1;
                if (r < 2)      v = 0.5f * W_ih[t*80 + j*2 + d];          // i
                else if (r < 4) v =        W_ih[t*80 + (20 + j)*2 + d];   // g
                else            v = 0.5f * W_ih[t*80 + (30 + j)*2 + d];   // o
            } else if (r == 6) v = 0.5f * (b_ih[t*40 + j]      + b_hh[t*40 + j]);
            else if   (r == 7) v =        (b_ih[t*40 + 20 + j] + b_hh[t*40 + 20 + j]);
            else if   (r == 8) v = 0.5f * (b_ih[t*40 + 30 + j] + b_hh[t*40 + 30 + j]);
            else if   (r == 9) v = W_fc[t*20 + j];        // d=0 row
            else               v = W_fc[t*20 + 10 + j];   // d=1 row
        } else {
            v = b_fc[t*2 + (off - 110)];
        }
        wsh[t * PSU + off] = make_float2(v, v);
    }
    __syncthreads();

    int g = blockIdx.x * BLOCK + threadIdx.x;        // 0 .. 1376255
    int t = g % T_LEADS;                             // lead constant across NB
    const u64* wt = (const u64*)&wsh[t * PSU];
    const float2* x2 = (const float2*)x;
    float2* yo = (float2*)y_out;

    const u64 HALF2 = pk(0.5f, 0.5f);
    const u64 CA4 = pk(PA4, PA4), CA3 = pk(PA3, PA3), CA2 = pk(PA2, PA2),
              CA1 = pk(PA1, PA1), CA0 = pk(PA0, PA0);

    u64 X0[2], X1[2], Y0[2], Y1[2];
    {
        u64 BF0 = wt[110], BF1 = wt[111];
        #pragma unroll
        for (int p = 0; p < 2; p++) {
            float2 a = x2[g + (2*p)     * NTH_TOTAL];
            float2 b = x2[g + (2*p + 1) * NTH_TOTAL];
            X0[p] = pk(a.x, b.x);
            X1[p] = pk(a.y, b.y);
            Y0[p] = BF0;
            Y1[p] = BF1;
        }
    }

    #pragma unroll 1
    for (int j = 0; j < HID; j++) {
        u64 WI0 = wt[0], WI1 = wt[1], WG0 = wt[2], WG1 = wt[3];
        u64 WO0 = wt[4], WO1 = wt[5];
        u64 BI  = wt[6], BG  = wt[7], BO  = wt[8];
        u64 F0  = wt[9], F1  = wt[10];
        wt += 11;

        #pragma unroll
        for (int p = 0; p < 2; p++) {
            u64 ZI = fma2(WI0, X0[p], fma2(WI1, X1[p], BI)); // pre-halved
            u64 ZG = fma2(WG0, X0[p], fma2(WG1, X1[p], BG));
            u64 ZO = fma2(WO0, X0[p], fma2(WO1, X1[p], BO)); // pre-halved
            float zi0, zi1, zg0, zg1, zo0, zo1;
            upk(ZI, zi0, zi1); upk(ZG, zg0, zg1); upk(ZO, zo0, zo1);
            u64 TI = pk(tanh_apx(zi0), tanh_apx(zi1));
            u64 TG = pk(tanh_apx(zg0), tanh_apx(zg1));
            u64 TO = pk(tanh_apx(zo0), tanh_apx(zo1));
            u64 SI = fma2(TI, HALF2, HALF2);   // sigmoid(i)
            u64 SO = fma2(TO, HALF2, HALF2);   // sigmoid(o)
            u64 C  = mul2(SI, TG);             // c, |c| < 1
            u64 U  = mul2(C, C);
            u64 P  = fma2(U, CA4, CA3);        // tanh(c)/c via poly
            P = fma2(P, U, CA2);
            P = fma2(P, U, CA1);
            P = fma2(P, U, CA0);
            u64 SC = mul2(SO, C);
            u64 H  = mul2(SC, P);              // h = sigmoid(o)*tanh(c)
            Y0[p] = fma2(F0, H, Y0[p]);
            Y1[p] = fma2(F1, H, Y1[p]);
        }
    }

    #pragma unroll
    for (int p = 0; p < 2; p++) {
        float ya0, yb0, ya1, yb1;
        upk(Y0[p], ya0, yb0);
        upk(Y1[p], ya1, yb1);
        yo[g + (2*p)     * NTH_TOTAL] = make_float2(ya0, ya1);
        yo[g + (2*p + 1) * NTH_TOTAL] = make_float2(yb0, yb1);
    }
}

extern "C" void kernel_launch(void* const* d_in, const int* in_sizes, int n_in,
                              void* d_out, int out_size) {
    perlead_lstm_kernel<<<NTH_TOTAL / BLOCK, BLOCK>>>(
        (const float*)d_in[0],   // x
        (const float*)d_in[1],   // W_ih
        (const float*)d_in[2],   // b_ih
        (const float*)d_in[3],   // b_hh
        (const float*)d_in[4],   // W_fc
        (const float*)d_in[5],   // b_fc
        (float*)d_out);
}

// round 11
// speedup vs baseline: 1.8827x; 1.8827x over previous
#include <cuda_runtime.h>

// PerLeadTimeLSTM: B=131072, LEADS=42, INPUT_DIM=2, HIDDEN=10.
// f-gate dead (c0=0):  y = W_fc @ (sigmoid(o) * tanh(sigmoid(i)*tanh(g))) + b_fc
// R11 = R7 resubmitted verbatim (R7-R10 all hit GPU-broker capacity timeouts;
// this source has never run). Proven scalar arithmetic (R1) + occupancy push:
//   - NB=4 (16 data regs instead of 32), full j-unroll, scalar smem weights
//   - __launch_bounds__(256,5) -> <=51 regs, ~62% occupancy
// f32x2 packing abandoned (R4/R6: 2.2-2.5x slower — pack/unpack ALU overhead,
// no real FFMA2 win). 4 MUFU/elem, sigmoid via tanh identity.

#define B_TOT   131072
#define T_LEADS 42
#define HID     10
#define NB      4
#define NTH_TOTAL (B_TOT * T_LEADS / NB)   // 1376256 threads, exact
#define BLOCK   256
#define PS      113   // padded smem stride (floats); scalar LDS only

__device__ __forceinline__ float tanh_apx(float x) {
    float r;
    asm("tanh.approx.f32 %0, %1;" : "=f"(r) : "f"(x));
    return r;
}

__global__ __launch_bounds__(BLOCK, 5)
void perlead_lstm_kernel(
    const float* __restrict__ x,      // (B, 42, 2)
    const float* __restrict__ W_ih,   // (42, 40, 2)
    const float* __restrict__ b_ih,   // (42, 40)
    const float* __restrict__ b_hh,   // (42, 40)
    const float* __restrict__ W_fc,   // (42, 2, 10)
    const float* __restrict__ b_fc,   // (42, 2)
    float* __restrict__ y_out)        // (B, 42, 2)
{
    __shared__ float w[T_LEADS * PS];

    // Fold weights into smem. Per-lead layout (floats):
    //  [0..19] w_i*0.5 | [20..39] w_g | [40..59] w_o*0.5
    //  [60..69] 0.5*(b_ih+b_hh)_i | [70..79] (b_ih+b_hh)_g | [80..89] 0.5*(..)_o
    //  [90..109] w_fc pairs (d0_j,d1_j) | [110..111] b_fc
    for (int idx = threadIdx.x; idx < T_LEADS * 112; idx += BLOCK) {
        int t = idx / 112;
        int off = idx % 112;
        float v;
        if (off < 20) {
            int j = off >> 1, d = off & 1;
            v = 0.5f * W_ih[t*80 + j*2 + d];
        } else if (off < 40) {
            int o2 = off - 20; int j = o2 >> 1, d = o2 & 1;
            v = W_ih[t*80 + (20 + j)*2 + d];
        } else if (off < 60) {
            int o2 = off - 40; int j = o2 >> 1, d = o2 & 1;
            v = 0.5f * W_ih[t*80 + (30 + j)*2 + d];
        } else if (off < 70) {
            int j = off - 60;
            v = 0.5f * (b_ih[t*40 + j] + b_hh[t*40 + j]);
        } else if (off < 80) {
            int j = off - 70;
            v = b_ih[t*40 + 20 + j] + b_hh[t*40 + 20 + j];
        } else if (off < 90) {
            int j = off - 80;
            v = 0.5f * (b_ih[t*40 + 30 + j] + b_hh[t*40 + 30 + j]);
        } else if (off < 110) {
            int o2 = off - 90; int j = o2 >> 1, d = o2 & 1;
            v = W_fc[t*20 + d*10 + j];
        } else {
            v = b_fc[t*2 + (off - 110)];
        }
        w[t * PS + off] = v;
    }
    __syncthreads();

    int g = blockIdx.x * BLOCK + threadIdx.x;        // 0 .. 1376255
    int t = g % T_LEADS;                             // lead constant across NB
    const float* wt = &w[t * PS];

    float x0[NB], x1[NB], y0[NB], y1[NB];
    const float2* x2 = (const float2*)x;
    float bf0 = wt[110], bf1 = wt[111];

    #pragma unroll
    for (int k = 0; k < NB; k++) {
        float2 xv = x2[g + k * NTH_TOTAL];
        x0[k] = xv.x; x1[k] = xv.y;
        y0[k] = bf0;  y1[k] = bf1;
    }

    #pragma unroll
    for (int j = 0; j < HID; j++) {
        float wi0 = wt[2*j],      wi1 = wt[2*j + 1];
        float wg0 = wt[20 + 2*j], wg1 = wt[21 + 2*j];
        float wo0 = wt[40 + 2*j], wo1 = wt[41 + 2*j];
        float bi  = wt[60 + j],   bg  = wt[70 + j],  bo = wt[80 + j];
        float f0  = wt[90 + 2*j], f1  = wt[91 + 2*j];
        #pragma unroll
        for (int k = 0; k < NB; k++) {
            float zi = fmaf(wi1, x1[k], fmaf(wi0, x0[k], bi));  // pre-halved
            float zg = fmaf(wg1, x1[k], fmaf(wg0, x0[k], bg));
            float zo = fmaf(wo1, x1[k], fmaf(wo0, x0[k], bo));  // pre-halved
            float si = fmaf(0.5f, tanh_apx(zi), 0.5f);          // sigmoid(i)
            float tg = tanh_apx(zg);
            float c  = si * tg;
            float tc = tanh_apx(c);
            float so = fmaf(0.5f, tanh_apx(zo), 0.5f);          // sigmoid(o)
            float h  = so * tc;
            y0[k] = fmaf(f0, h, y0[k]);
            y1[k] = fmaf(f1, h, y1[k]);
        }
    }

    float2* yo = (float2*)y_out;
    #pragma unroll
    for (int k = 0; k < NB; k++) {
        yo[g + k * NTH_TOTAL] = make_float2(y0[k], y1[k]);
    }
}

extern "C" void kernel_launch(void* const* d_in, const int* in_sizes, int n_in,
                              void* d_out, int out_size) {
    perlead_lstm_kernel<<<NTH_TOTAL / BLOCK, BLOCK>>>(
        (const float*)d_in[0],   // x
        (const float*)d_in[1],   // W_ih
        (const float*)d_in[2],   // b_ih
        (const float*)d_in[3],   // b_hh
        (const float*)d_in[4],   // W_fc
        (const float*)d_in[5],   // b_fc
        (float*)d_out);
}

// round 16
// speedup vs baseline: 2.5156x; 1.3362x over previous
#include <cuda_runtime.h>

// PerLeadTimeLSTM: B=131072, LEADS=42, INPUT_DIM=2, HIDDEN=10.
// f-gate dead (c0=0):  y = W_fc @ (sigmoid(o) * tanh(sigmoid(i)*tanh(g))) + b_fc
// R16 = R12 resubmitted verbatim (R12-R15 hit GPU-broker capacity timeouts;
// this source has never run). R1 source with EXACTLY ONE change:
// __launch_bounds__(256,5). R7/R11 showed NB=4 doubles per-element fixed
// costs (alu 26->39%, L1 29->41%) and regresses to 100us despite occ 59% —
// so keep NB=8 (R1's amortization) and raise occupancy via reg cap alone:
// 51 regs -> 5 blocks/SM (~58% occ).
// 4 MUFU/elem, sigmoid via tanh identity, scalar smem weights (PS=113).

#define B_TOT   131072
#define T_LEADS 42
#define HID     10
#define NB      8
#define NTH_TOTAL (B_TOT * T_LEADS / NB)   // 688128 threads, exact
#define BLOCK   256
#define PS      113   // padded smem stride (floats); scalar LDS only

__device__ __forceinline__ float tanh_apx(float x) {
    float r;
    asm("tanh.approx.f32 %0, %1;" : "=f"(r) : "f"(x));
    return r;
}

__global__ __launch_bounds__(BLOCK, 5)
void perlead_lstm_kernel(
    const float* __restrict__ x,      // (B, 42, 2)
    const float* __restrict__ W_ih,   // (42, 40, 2)
    const float* __restrict__ b_ih,   // (42, 40)
    const float* __restrict__ b_hh,   // (42, 40)
    const float* __restrict__ W_fc,   // (42, 2, 10)
    const float* __restrict__ b_fc,   // (42, 2)
    float* __restrict__ y_out)        // (B, 42, 2)
{
    __shared__ float w[T_LEADS * PS];

    // Fold weights into smem. Per-lead layout (floats):
    //  [0..19] w_i*0.5 | [20..39] w_g | [40..59] w_o*0.5
    //  [60..69] 0.5*(b_ih+b_hh)_i | [70..79] (b_ih+b_hh)_g | [80..89] 0.5*(..)_o
    //  [90..109] w_fc pairs (d0_j,d1_j) | [110..111] b_fc
    for (int idx = threadIdx.x; idx < T_LEADS * 112; idx += BLOCK) {
        int t = idx / 112;
        int off = idx % 112;
        float v;
        if (off < 20) {
            int j = off >> 1, d = off & 1;
            v = 0.5f * W_ih[t*80 + j*2 + d];
        } else if (off < 40) {
            int o2 = off - 20; int j = o2 >> 1, d = o2 & 1;
            v = W_ih[t*80 + (20 + j)*2 + d];
        } else if (off < 60) {
            int o2 = off - 40; int j = o2 >> 1, d = o2 & 1;
            v = 0.5f * W_ih[t*80 + (30 + j)*2 + d];
        } else if (off < 70) {
            int j = off - 60;
            v = 0.5f * (b_ih[t*40 + j] + b_hh[t*40 + j]);
        } else if (off < 80) {
            int j = off - 70;
            v = b_ih[t*40 + 20 + j] + b_hh[t*40 + 20 + j];
        } else if (off < 90) {
            int j = off - 80;
            v = 0.5f * (b_ih[t*40 + 30 + j] + b_hh[t*40 + 30 + j]);
        } else if (off < 110) {
            int o2 = off - 90; int j = o2 >> 1, d = o2 & 1;
            v = W_fc[t*20 + d*10 + j];
        } else {
            v = b_fc[t*2 + (off - 110)];
        }
        w[t * PS + off] = v;
    }
    __syncthreads();

    int g = blockIdx.x * BLOCK + threadIdx.x;        // 0 .. 688127
    int t = g % T_LEADS;                             // same lead for all NB elems
    const float* wt = &w[t * PS];

    float x0[NB], x1[NB], y0[NB], y1[NB];
    const float2* x2 = (const float2*)x;
    float bf0 = wt[110], bf1 = wt[111];

    #pragma unroll
    for (int k = 0; k < NB; k++) {
        float2 xv = x2[g + k * NTH_TOTAL];
        x0[k] = xv.x; x1[k] = xv.y;
        y0[k] = bf0;  y1[k] = bf1;
    }

    #pragma unroll
    for (int j = 0; j < HID; j++) {
        float wi0 = wt[2*j],      wi1 = wt[2*j + 1];
        float wg0 = wt[20 + 2*j], wg1 = wt[21 + 2*j];
        float wo0 = wt[40 + 2*j], wo1 = wt[41 + 2*j];
        float bi  = wt[60 + j],   bg  = wt[70 + j],  bo = wt[80 + j];
        float f0  = wt[90 + 2*j], f1  = wt[91 + 2*j];
        #pragma unroll
        for (int k = 0; k < NB; k++) {
            float zi = fmaf(wi1, x1[k], fmaf(wi0, x0[k], bi));  // pre-halved
            float zg = fmaf(wg1, x1[k], fmaf(wg0, x0[k], bg));
            float zo = fmaf(wo1, x1[k], fmaf(wo0, x0[k], bo));  // pre-halved
            float si = fmaf(0.5f, tanh_apx(zi), 0.5f);          // sigmoid(i)
            float tg = tanh_apx(zg);
            float c  = si * tg;
            float tc = tanh_apx(c);
            float so = fmaf(0.5f, tanh_apx(zo), 0.5f);          // sigmoid(o)
            float h  = so * tc;
            y0[k] = fmaf(f0, h, y0[k]);
            y1[k] = fmaf(f1, h, y1[k]);
        }
    }

    float2* yo = (float2*)y_out;
    #pragma unroll
    for (int k = 0; k < NB; k++) {
        yo[g + k * NTH_TOTAL] = make_float2(y0[k], y1[k]);
    }
}

extern "C" void kernel_launch(void* const* d_in, const int* in_sizes, int n_in,
                              void* d_out, int out_size) {
    perlead_lstm_kernel<<<NTH_TOTAL / BLOCK, BLOCK>>>(
        (const float*)d_in[0],   // x
        (const float*)d_in[1],   // W_ih
        (const float*)d_in[2],   // b_ih
        (const float*)d_in[3],   // b_hh
        (const float*)d_in[4],   // W_fc
        (const float*)d_in[5],   // b_fc
        (float*)d_out);
}